// round 10
// baseline (speedup 1.0000x reference)
#include <cuda_runtime.h>
#include <cuda_bf16.h>

#define NB 8
#define NPTS 16384
#define NQ 1024
#define NC 64
#define NS 32
#define R2 0.04f

// 2 MB scratch: xyz packed as float4 for single-LDG.128 scan loads.
__device__ float4 g_xyz4[(size_t)NB * NPTS];
// 33.5 MB scratch: features transposed to (B, N, C); fits in L2 (126 MB).
__device__ float g_feats_t[(size_t)NB * NPTS * NC];
// 1 MB scratch: padded neighbor indices per query.
__device__ int g_idx[(size_t)NB * NQ * NS];

#define TBLOCKS (NB * (NPTS / 32))      // 4096 transpose tiles
#define PBLOCKS ((NB * NPTS) / 256)     // 512 pack blocks

// ---- transpose (B,C,N) -> (B,N,C) (side stream, overlaps the scan) ----
__global__ __launch_bounds__(256) void transpose_kernel(const float* __restrict__ feats) {
    __shared__ float tile[32][65];
    const int b  = blockIdx.x >> 9;          // / (NPTS/32)
    const int n0 = (blockIdx.x & 511) * 32;
    const int t  = threadIdx.x;
    const int tx = t & 31;
    const int ty = t >> 5;

    const float* src = feats + (size_t)b * NC * NPTS + n0;
    #pragma unroll
    for (int k = 0; k < 8; ++k) {
        const int c = ty * 8 + k;
        tile[tx][c] = src[(size_t)c * NPTS + tx];
    }
    __syncthreads();

    float* dst = g_feats_t + ((size_t)b * NPTS + n0) * NC;
    #pragma unroll
    for (int k = 0; k < 8; ++k) {
        const int idx = k * 256 + t;
        const int n = idx >> 6;
        const int c = idx & 63;
        dst[(size_t)n * NC + c] = tile[n][c];
    }
}

// ---- pack (B,N,3) f32 -> (B,N) float4 (main stream, before scan) ----
__global__ __launch_bounds__(256) void pack_xyz_kernel(const float* __restrict__ xyz) {
    __shared__ float sbuf[8][96];
    const int warp = threadIdx.x >> 5, lane = threadIdx.x & 31;
    const size_t base = (size_t)blockIdx.x * 256 + warp * 32;
    const float* src = xyz + base * 3;
    float* s = sbuf[warp];
    s[lane]      = src[lane];
    s[lane + 32] = src[lane + 32];
    s[lane + 64] = src[lane + 64];
    __syncwarp();
    g_xyz4[base + lane] = make_float4(s[lane * 3], s[lane * 3 + 1], s[lane * 3 + 2], 0.f);
}

// ---- scan: one block (4 warps) per query; 1024 pts/round ----
// Writes grouped-xyz channels + padded idx to g_idx. No features.
__global__ __launch_bounds__(128) void scan_kernel(
    const float* __restrict__ new_xyz,  // (B, S, 3)
    float* __restrict__ out)            // (B, 3+C, S, NS)
{
    const int lane = threadIdx.x & 31;
    const int w    = threadIdx.x >> 5;         // warp id 0..3
    const int q = blockIdx.x;                  // one query per block
    const int b = q >> 10;                     // / NQ
    const int s = q & (NQ - 1);

    // 31 carried + up to 1024 appended in the crossing round: unchecked stores.
    __shared__ int idx_buf[NS + 1024];
    __shared__ int wtot[2][4];                 // double-buffered per-warp counts

    const float qx = new_xyz[q * 3 + 0];
    const float qy = new_xyz[q * 3 + 1];
    const float qz = new_xyz[q * 3 + 2];

    const float4* __restrict__ xb4 = g_xyz4 + (size_t)b * NPTS;
    const unsigned lt = (1u << lane) - 1u;

    int cnt = 0;
    int pb = 0;
    for (int j0 = 0; j0 < NPTS; j0 += 1024) {
        const int jw = j0 + w * 256;
        float4 p[8];
        #pragma unroll
        for (int u = 0; u < 8; ++u) p[u] = xb4[jw + u * 32 + lane];

        bool wi[8];
        #pragma unroll
        for (int u = 0; u < 8; ++u) {
            const float dx = p[u].x - qx;
            const float dy = p[u].y - qy;
            const float dz = p[u].z - qz;
            wi[u] = dx * dx + dy * dy + dz * dz < R2;
        }
        unsigned m[8];
        #pragma unroll
        for (int u = 0; u < 8; ++u) m[u] = __ballot_sync(0xFFFFFFFFu, wi[u]);

        int tot = 0;
        #pragma unroll
        for (int u = 0; u < 8; ++u) tot += __popc(m[u]);
        if (lane == 0) wtot[pb][w] = tot;
        __syncthreads();

        int base = cnt;
        #pragma unroll
        for (int ww = 0; ww < 4; ++ww) {
            const int t = wtot[pb][ww];
            if (ww < w) base += t;
            cnt += t;
        }
        #pragma unroll
        for (int u = 0; u < 8; ++u) {
            if (wi[u]) idx_buf[base + __popc(m[u] & lt)] = jw + u * 32 + lane;
            base += __popc(m[u]);
        }
        pb ^= 1;
        if (cnt >= NS) break;   // uniform across block
    }
    __syncthreads();            // idx_buf (final round) visible

    const int eff = cnt < NS ? cnt : NS;
    const int first = (eff > 0) ? idx_buf[0] : 0;

    if (w == 0) {
        const int im = (lane < eff) ? idx_buf[lane] : first;
        g_idx[(size_t)q * NS + lane] = im;     // padded index for gather kernel

        const float4 P = xb4[im];
        const size_t CH = (size_t)NQ * NS;
        float* ob = out + ((size_t)b * (3 + NC) * NQ + s) * NS + lane;
        ob[0 * CH] = P.x - qx;
        ob[1 * CH] = P.y - qy;
        ob[2 * CH] = P.z - qz;
    }
}

#define FSTRIDE 68   // fsm row stride in floats: conflict-free STS.128/LDS.128

// ---- gather: one block (4 warps) per query; features only ----
__global__ __launch_bounds__(128) void gather_kernel(float* __restrict__ out) {
    const int lane = threadIdx.x & 31;
    const int w    = threadIdx.x >> 5;
    const int q = blockIdx.x;
    const int b = q >> 10;
    const int s = q & (NQ - 1);

    __shared__ float fsm[NS * FSTRIDE];        // [sample][channel]

    // half-warp per sample row: warp w loads samples 8w..8w+7,
    // lane g=lane&15 owns float4 channel-group g.
    const float4* __restrict__ fbase = (const float4*)(g_feats_t + (size_t)b * NPTS * NC);
    const int g    = lane & 15;
    const int half = lane >> 4;
    #pragma unroll
    for (int i = 0; i < 4; ++i) {
        const int msamp = 8 * w + 2 * i + half;
        const int im = g_idx[(size_t)q * NS + msamp];
        const float4 v = __ldg(fbase + (size_t)im * (NC / 4) + g);
        *(float4*)&fsm[msamp * FSTRIDE + 4 * g] = v;   // STS.128, conflict-free
    }
    __syncthreads();

    const size_t CH = (size_t)NQ * NS;
    float* of = out + ((size_t)b * (3 + NC) * NQ + s) * NS + lane + 3 * CH;
    #pragma unroll
    for (int c4 = 0; c4 < 4; ++c4) {
        const int ch0 = 16 * w + 4 * c4;
        const float4 fv = *(const float4*)&fsm[lane * FSTRIDE + ch0];  // LDS.128
        of[(size_t)(ch0 + 0) * CH] = fv.x;
        of[(size_t)(ch0 + 1) * CH] = fv.y;
        of[(size_t)(ch0 + 2) * CH] = fv.z;
        of[(size_t)(ch0 + 3) * CH] = fv.w;
    }
}

static cudaStream_t g_side = nullptr;
static cudaEvent_t  g_fork = nullptr, g_join = nullptr;

extern "C" void kernel_launch(void* const* d_in, const int* in_sizes, int n_in,
                              void* d_out, int out_size) {
    const float* xyz     = (const float*)d_in[0];
    const float* new_xyz = (const float*)d_in[1];
    const float* feats   = (const float*)d_in[2];
    float* out = (float*)d_out;

    if (g_side == nullptr) {   // one-time resource setup (first call = correctness
        cudaStreamCreateWithFlags(&g_side, cudaStreamNonBlocking);  // run, pre-capture)
        cudaEventCreateWithFlags(&g_fork, cudaEventDisableTiming);
        cudaEventCreateWithFlags(&g_join, cudaEventDisableTiming);
    }

    // fork: transpose runs on side stream, concurrent with pack + scan
    cudaEventRecord(g_fork, 0);
    cudaStreamWaitEvent(g_side, g_fork, 0);
    transpose_kernel<<<TBLOCKS, 256, 0, g_side>>>(feats);
    cudaEventRecord(g_join, g_side);

    pack_xyz_kernel<<<PBLOCKS, 256>>>(xyz);
    scan_kernel<<<NB * NQ, 128>>>(new_xyz, out);

    // join: gather needs both the transpose and the scan
    cudaStreamWaitEvent(0, g_join, 0);
    gather_kernel<<<NB * NQ, 128>>>(out);
}

// round 11
// speedup vs baseline: 1.0438x; 1.0438x over previous
#include <cuda_runtime.h>
#include <cuda_bf16.h>

#define NB 8
#define NPTS 16384
#define NQ 1024
#define NC 64
#define NS 32
#define R2 0.04f

// 2 MB scratch: xyz packed as float4 for single-LDG.128 scan loads.
__device__ float4 g_xyz4[(size_t)NB * NPTS];
// 33.5 MB scratch: features transposed to (B, N, C); fits in L2 (126 MB).
__device__ float g_feats_t[(size_t)NB * NPTS * NC];

#define TBLOCKS (NB * (NPTS / 32))      // 4096 transpose tiles
#define PBLOCKS ((NB * NPTS) / 256)     // 512 pack blocks

// ---- fused pre-pass: feats transpose + xyz pack (job by blockIdx.x) ----
__global__ __launch_bounds__(256) void prepass_kernel(
    const float* __restrict__ xyz, const float* __restrict__ feats)
{
    if (blockIdx.x < TBLOCKS) {
        __shared__ float tile[32][65];
        const int b  = blockIdx.x >> 9;          // / (NPTS/32)
        const int n0 = (blockIdx.x & 511) * 32;
        const int t  = threadIdx.x;
        const int tx = t & 31;
        const int ty = t >> 5;

        const float* src = feats + (size_t)b * NC * NPTS + n0;
        #pragma unroll
        for (int k = 0; k < 8; ++k) {
            const int c = ty * 8 + k;
            tile[tx][c] = src[(size_t)c * NPTS + tx];
        }
        __syncthreads();

        float* dst = g_feats_t + ((size_t)b * NPTS + n0) * NC;
        #pragma unroll
        for (int k = 0; k < 8; ++k) {
            const int idx = k * 256 + t;
            const int n = idx >> 6;
            const int c = idx & 63;
            dst[(size_t)n * NC + c] = tile[n][c];
        }
    } else {
        __shared__ float sbuf[8][96];
        const int bid  = blockIdx.x - TBLOCKS;
        const int warp = threadIdx.x >> 5, lane = threadIdx.x & 31;
        const size_t base = (size_t)bid * 256 + warp * 32;
        const float* src = xyz + base * 3;
        float* s = sbuf[warp];
        s[lane]      = src[lane];
        s[lane + 32] = src[lane + 32];
        s[lane + 64] = src[lane + 64];
        __syncwarp();
        g_xyz4[base + lane] = make_float4(s[lane * 3], s[lane * 3 + 1], s[lane * 3 + 2], 0.f);
    }
}

#define FSTRIDE 68   // fsm row stride in floats: conflict-free STS.128/LDS.128

// ---- main: one block (4 warps) per 2 queries; shared point loads ----
__global__ __launch_bounds__(128) void qag_kernel(
    const float* __restrict__ new_xyz,  // (B, S, 3)
    float* __restrict__ out)            // (B, 3+C, S, NS)
{
    const int lane = threadIdx.x & 31;
    const int w    = threadIdx.x >> 5;         // warp id 0..3
    const int q0 = blockIdx.x * 2;             // two queries per block (same b)
    const int b  = q0 >> 10;
    const int s0 = q0 & (NQ - 1);

    __shared__ int   idx_buf[2][NS + 1024];    // per-query, unchecked appends
    __shared__ int   wtot[2][2][4];            // [pingpong][query][warp]
    __shared__ float fsm[2][NS * FSTRIDE];     // [query][sample][channel]

    const float qx0 = new_xyz[q0 * 3 + 0];
    const float qy0 = new_xyz[q0 * 3 + 1];
    const float qz0 = new_xyz[q0 * 3 + 2];
    const float qx1 = new_xyz[q0 * 3 + 3];
    const float qy1 = new_xyz[q0 * 3 + 4];
    const float qz1 = new_xyz[q0 * 3 + 5];

    const float4* __restrict__ xb4 = g_xyz4 + (size_t)b * NPTS;
    const unsigned lt = (1u << lane) - 1u;

    // ---- ball query: 1024-pt rounds; loads shared by both queries ----
    int cnt0 = 0, cnt1 = 0;
    int pb = 0;
    for (int j0 = 0; j0 < NPTS; j0 += 1024) {
        const int jw = j0 + w * 256;
        float4 p[8];
        #pragma unroll
        for (int u = 0; u < 8; ++u) p[u] = xb4[jw + u * 32 + lane];

        const bool act0 = cnt0 < NS;           // uniform across block
        const bool act1 = cnt1 < NS;

        unsigned m0[8], m1[8];
        bool wi0[8], wi1[8];
        int tot0 = 0, tot1 = 0;
        if (act0) {
            #pragma unroll
            for (int u = 0; u < 8; ++u) {
                const float dx = p[u].x - qx0;
                const float dy = p[u].y - qy0;
                const float dz = p[u].z - qz0;
                wi0[u] = dx * dx + dy * dy + dz * dz < R2;
            }
            #pragma unroll
            for (int u = 0; u < 8; ++u) { m0[u] = __ballot_sync(0xFFFFFFFFu, wi0[u]); tot0 += __popc(m0[u]); }
        }
        if (act1) {
            #pragma unroll
            for (int u = 0; u < 8; ++u) {
                const float dx = p[u].x - qx1;
                const float dy = p[u].y - qy1;
                const float dz = p[u].z - qz1;
                wi1[u] = dx * dx + dy * dy + dz * dz < R2;
            }
            #pragma unroll
            for (int u = 0; u < 8; ++u) { m1[u] = __ballot_sync(0xFFFFFFFFu, wi1[u]); tot1 += __popc(m1[u]); }
        }
        if (lane == 0) { wtot[pb][0][w] = tot0; wtot[pb][1][w] = tot1; }
        __syncthreads();

        if (act0) {
            int base = cnt0;
            #pragma unroll
            for (int ww = 0; ww < 4; ++ww) {
                const int t = wtot[pb][0][ww];
                if (ww < w) base += t;
                cnt0 += t;
            }
            #pragma unroll
            for (int u = 0; u < 8; ++u) {
                if (wi0[u]) idx_buf[0][base + __popc(m0[u] & lt)] = jw + u * 32 + lane;
                base += __popc(m0[u]);
            }
        }
        if (act1) {
            int base = cnt1;
            #pragma unroll
            for (int ww = 0; ww < 4; ++ww) {
                const int t = wtot[pb][1][ww];
                if (ww < w) base += t;
                cnt1 += t;
            }
            #pragma unroll
            for (int u = 0; u < 8; ++u) {
                if (wi1[u]) idx_buf[1][base + __popc(m1[u] & lt)] = jw + u * 32 + lane;
                base += __popc(m1[u]);
            }
        }
        pb ^= 1;
        if (cnt0 >= NS && cnt1 >= NS) break;   // uniform across block
    }
    __syncthreads();            // final-round idx_buf visible

    const int eff0 = cnt0 < NS ? cnt0 : NS;
    const int eff1 = cnt1 < NS ? cnt1 : NS;
    const int first0 = (eff0 > 0) ? idx_buf[0][0] : 0;
    const int first1 = (eff1 > 0) ? idx_buf[1][0] : 0;

    const size_t CH = (size_t)NQ * NS;
    float* ob0 = out + ((size_t)b * (3 + NC) * NQ + s0) * NS + lane;
    float* ob1 = ob0 + NS;      // s1 = s0 + 1

    // ---- grouped xyz: warp 0 -> q0, warp 1 -> q1 ----
    if (w == 0) {
        const int im = (lane < eff0) ? idx_buf[0][lane] : first0;
        const float4 P = xb4[im];
        ob0[0 * CH] = P.x - qx0;
        ob0[1 * CH] = P.y - qy0;
        ob0[2 * CH] = P.z - qz0;
    } else if (w == 1) {
        const int im = (lane < eff1) ? idx_buf[1][lane] : first1;
        const float4 P = xb4[im];
        ob1[0 * CH] = P.x - qx1;
        ob1[1 * CH] = P.y - qy1;
        ob1[2 * CH] = P.z - qz1;
    }

    // ---- grouped features: half-warp per row, both queries (8 LDG.128/warp) ----
    {
        const float4* __restrict__ fbase = (const float4*)(g_feats_t + (size_t)b * NPTS * NC);
        const int g    = lane & 15;
        const int half = lane >> 4;
        #pragma unroll
        for (int i = 0; i < 4; ++i) {
            const int msamp = 8 * w + 2 * i + half;
            const int im0 = (msamp < eff0) ? idx_buf[0][msamp] : first0;
            const int im1 = (msamp < eff1) ? idx_buf[1][msamp] : first1;
            const float4 v0 = __ldg(fbase + (size_t)im0 * (NC / 4) + g);
            const float4 v1 = __ldg(fbase + (size_t)im1 * (NC / 4) + g);
            *(float4*)&fsm[0][msamp * FSTRIDE + 4 * g] = v0;
            *(float4*)&fsm[1][msamp * FSTRIDE + 4 * g] = v1;
        }
    }
    __syncthreads();

    // ---- writeout: warp w covers channels 16w..16w+15, lane = sample ----
    float* of0 = ob0 + 3 * CH;
    float* of1 = ob1 + 3 * CH;
    #pragma unroll
    for (int c4 = 0; c4 < 4; ++c4) {
        const int ch0 = 16 * w + 4 * c4;
        const float4 f0 = *(const float4*)&fsm[0][lane * FSTRIDE + ch0];
        const float4 f1 = *(const float4*)&fsm[1][lane * FSTRIDE + ch0];
        of0[(size_t)(ch0 + 0) * CH] = f0.x;
        of0[(size_t)(ch0 + 1) * CH] = f0.y;
        of0[(size_t)(ch0 + 2) * CH] = f0.z;
        of0[(size_t)(ch0 + 3) * CH] = f0.w;
        of1[(size_t)(ch0 + 0) * CH] = f1.x;
        of1[(size_t)(ch0 + 1) * CH] = f1.y;
        of1[(size_t)(ch0 + 2) * CH] = f1.z;
        of1[(size_t)(ch0 + 3) * CH] = f1.w;
    }
}

extern "C" void kernel_launch(void* const* d_in, const int* in_sizes, int n_in,
                              void* d_out, int out_size) {
    const float* xyz     = (const float*)d_in[0];
    const float* new_xyz = (const float*)d_in[1];
    const float* feats   = (const float*)d_in[2];
    float* out = (float*)d_out;

    prepass_kernel<<<TBLOCKS + PBLOCKS, 256>>>(xyz, feats);

    qag_kernel<<<(NB * NQ) / 2, 128>>>(new_xyz, out);   // 2 queries per block
}